// round 12
// baseline (speedup 1.0000x reference)
#include <cuda_runtime.h>
#include <cuda_bf16.h>
#include <cstdint>

#define Bc    64
#define Tc    1000
#define Fc    512
#define Hc    8
#define KDc   32
#define NCc   8
#define CHUNK 125           // Tc / NCc
#define NT    16            // tiles per chunk (15 full x8 + 1 x5)
#define SCALE 0.17677669529663689f   // 1/sqrt(32)
#define NEGBIG (-3.4e38f)

// ---------------- device scratch (no allocation allowed) ----------------
__device__ float g_qpart[32][Hc * KDc];     // per-block partial qh sums
__device__ float g_wk[Hc][Fc];              // scale * (Wk @ qh), per head
__device__ float g_cb[Hc];                  // scale * (qh . bk)
__device__ float g_m[Bc][NCc][Hc];
__device__ float g_l[Bc][NCc][Hc];
__device__ float g_acc[Bc][Hc][NCc][Fc];    // 8.4 MB un-normalized weighted x sums
__device__ float g_ctx[Bc][Hc * KDc];
__device__ float g_pooled[Bc][Fc];

// ---------------- packed fp32x2 FMA (FFMA2) ----------------
__device__ __forceinline__ float2 fma2(float2 d, float2 a, float2 b) {
    unsigned long long dd, aa, bb;
    dd = *reinterpret_cast<unsigned long long*>(&d);
    aa = *reinterpret_cast<unsigned long long*>(&a);
    bb = *reinterpret_cast<unsigned long long*>(&b);
    asm("fma.rn.f32x2 %0, %1, %2, %0;" : "+l"(dd) : "l"(aa), "l"(bb));
    return *reinterpret_cast<float2*>(&dd);
}

__device__ __forceinline__ void cp16(unsigned int dst, const void* src) {
    asm volatile("cp.async.ca.shared.global [%0], [%1], 16;" :: "r"(dst), "l"(src));
}
#define CP_COMMIT() asm volatile("cp.async.commit_group;")
#define CP_WAIT1()  asm volatile("cp.async.wait_group 1;")

// ---------------- prep1 (#1): partial qh sums, 32 blocks over f-chunks ----------------
__global__ __launch_bounds__(256) void prep1_kernel(const float* __restrict__ q,
                                                    const float* __restrict__ Wq) {
    const int tid = threadIdx.x;
    const int f0 = blockIdx.x * 16;
    float qv[16];
#pragma unroll
    for (int ff = 0; ff < 16; ff++) qv[ff] = q[f0 + ff];
    float s = 0.f;
#pragma unroll
    for (int ff = 0; ff < 16; ff++)
        s = fmaf(qv[ff], Wq[(f0 + ff) * 256 + tid], s);
    g_qpart[blockIdx.x][tid] = s;
}

// ---------------- prep2 (#2): wk_eff[h][f] = scale * sum_k Wk[f,h,k]*qh[h,k] ----------------
__global__ __launch_bounds__(256) void prep2_kernel(const float* __restrict__ Wk,
                                                    const float* __restrict__ bq) {
    __shared__ float qh[Hc * KDc];
    const int tid = threadIdx.x;
    {
        float s = bq[tid];
#pragma unroll
        for (int i = 0; i < 32; i++) s += g_qpart[i][tid];
        qh[tid] = s;
    }
    __syncthreads();

    const int f0 = blockIdx.x * 8;
    const int o = tid >> 2;          // 0..63 : (frow, h)
    const int sub = tid & 3;         // k-quarter
    const int f = f0 + (o >> 3);
    const int h = o & 7;
    const float4* Wk4 = reinterpret_cast<const float4*>(Wk);
    float4 w0 = Wk4[f * 64 + h * 8 + sub * 2];
    float4 w1 = Wk4[f * 64 + h * 8 + sub * 2 + 1];
    const float* qp = &qh[h * 32 + sub * 8];
    float s = w0.x * qp[0] + w0.y * qp[1] + w0.z * qp[2] + w0.w * qp[3]
            + w1.x * qp[4] + w1.y * qp[5] + w1.z * qp[6] + w1.w * qp[7];
    s += __shfl_xor_sync(0xffffffffu, s, 1);
    s += __shfl_xor_sync(0xffffffffu, s, 2);
    if (sub == 0) g_wk[h][f] = s * SCALE;
}

// ---------------- prep_cb (#3): cb[h] = scale * (qh[h,:] . bk[h,:]) ----------------
__global__ __launch_bounds__(256) void prep_cb_kernel(const float* __restrict__ bk,
                                                      const float* __restrict__ bq) {
    __shared__ float qh[Hc * KDc];
    const int tid = threadIdx.x;
    {
        float s = bq[tid];
#pragma unroll
        for (int i = 0; i < 32; i++) s += g_qpart[i][tid];
        qh[tid] = s;
    }
    __syncthreads();
    if (tid < 8) {
        float c = 0.f;
        for (int k = 0; k < 32; k++) c += bk[tid * 32 + k] * qh[tid * 32 + k];
        g_cb[tid] = c * SCALE;
    }
}

// ---------------- main (#4): single-pass online-softmax, 2x score redundancy ----------------
__global__ __launch_bounds__(256, 3) void main_kernel(const float* __restrict__ x) {
    __shared__ __align__(16) float buf[2][8 * Fc];    // 32 KB double buffer
    __shared__ __align__(16) float sc_part[2][8][8];  // [f-half][row][head] partial dots
    __shared__ __align__(16) float pp[8][8];          // exp weights of current tile
    __shared__ __align__(16) float scl[8];            // per-head acc rescale
    const int tid = threadIdx.x;
    const int w = tid >> 5, lane = tid & 31;
    const int b = blockIdx.y, c = blockIdx.x;
    const float* xc = x + ((size_t)b * Tc + c * CHUNK) * Fc;

    const unsigned int buf0 = (unsigned int)__cvta_generic_to_shared(&buf[0][0]);
    const unsigned int buf1 = (unsigned int)__cvta_generic_to_shared(&buf[1][0]);

    // ---- score warp role: (f-half, head-quad, row-parity)
    const int hq = w & 1;            // heads 4hq..4hq+3
    const int fh = (w >> 1) & 1;     // f in [fh*256, fh*256+256)
    const int rp = w >> 2;           // rows {rp, rp+2, rp+4, rp+6}
    // per-lane wk: 4 heads x 8 f (f = fh*256 + 4*lane + {0..3, 128..131})
    float2 wk2[4][4];
#pragma unroll
    for (int i = 0; i < 4; i++) {
        float4 a0 = *reinterpret_cast<const float4*>(&g_wk[4 * hq + i][fh * 256 + 4 * lane]);
        float4 a1 = *reinterpret_cast<const float4*>(&g_wk[4 * hq + i][fh * 256 + 128 + 4 * lane]);
        wk2[i][0] = make_float2(a0.x, a0.y);
        wk2[i][1] = make_float2(a0.z, a0.w);
        wk2[i][2] = make_float2(a1.x, a1.y);
        wk2[i][3] = make_float2(a1.z, a1.w);
    }
    const float cbh = g_cb[w];       // head-w bias for the softmax stage

    // ---- prologue: preload tiles 0 and 1
    {
        const float4* src = reinterpret_cast<const float4*>(xc);
#pragma unroll
        for (int j = 0; j < 4; j++) cp16(buf0 + (tid + 256 * j) * 16, src + tid + 256 * j);
        CP_COMMIT();
#pragma unroll
        for (int j = 0; j < 4; j++) cp16(buf1 + (tid + 256 * j) * 16, src + 1024 + tid + 256 * j);
        CP_COMMIT();
    }

    float2 acc[8];
#pragma unroll
    for (int h = 0; h < 8; h++) acc[h] = make_float2(0.f, 0.f);
    float m_run = NEGBIG, l_run = 0.f;   // per-warp: warp w owns head w (lanes 0-7)

    for (int tile = 0; tile < NT; tile++) {
        const int rows = (tile == NT - 1) ? (CHUNK - 8 * (NT - 1)) : 8;
        float* tb = buf[tile & 1];

        CP_WAIT1();
        __syncthreads();

        // ---- score partials: warp covers 4 rows x 4 heads x 256 f (each x byte read 2x)
#pragma unroll
        for (int k = 0; k < 4; k++) {
            const int r = rp + 2 * k;
            if (r < rows) {
                const float* xr = tb + r * Fc + fh * 256 + 4 * lane;
                float4 x0 = *reinterpret_cast<const float4*>(xr);
                float4 x1 = *reinterpret_cast<const float4*>(xr + 128);
                float2 p[4];
#pragma unroll
                for (int i = 0; i < 4; i++) {
                    p[i] = make_float2(0.f, 0.f);
                    p[i] = fma2(p[i], make_float2(x0.x, x0.y), wk2[i][0]);
                    p[i] = fma2(p[i], make_float2(x0.z, x0.w), wk2[i][1]);
                    p[i] = fma2(p[i], make_float2(x1.x, x1.y), wk2[i][2]);
                    p[i] = fma2(p[i], make_float2(x1.z, x1.w), wk2[i][3]);
                }
                float s0 = p[0].x + p[0].y, s1 = p[1].x + p[1].y;
                float s2 = p[2].x + p[2].y, s3 = p[3].x + p[3].y;
#pragma unroll
                for (int off = 16; off; off >>= 1) {
                    s0 += __shfl_xor_sync(0xffffffffu, s0, off);
                    s1 += __shfl_xor_sync(0xffffffffu, s1, off);
                    s2 += __shfl_xor_sync(0xffffffffu, s2, off);
                    s3 += __shfl_xor_sync(0xffffffffu, s3, off);
                }
                if (lane == 0)
                    *reinterpret_cast<float4*>(&sc_part[fh][r][4 * hq]) =
                        make_float4(s0, s1, s2, s3);
            }
        }
        __syncthreads();

        // ---- online softmax, 8-way parallel: warp w = head w, lanes 0-7 = rows
        if (lane < 8) {
            const int h = w;
            float s = (lane < rows)
                    ? sc_part[0][lane][h] + sc_part[1][lane][h] + cbh
                    : NEGBIG;
            float mt = fmaxf(s, m_run);
#pragma unroll
            for (int off = 4; off; off >>= 1)
                mt = fmaxf(mt, __shfl_xor_sync(0x000000ffu, mt, off));
            float p = __expf(s - mt);          // 0 for padding lanes
            float ls = p;
#pragma unroll
            for (int off = 4; off; off >>= 1)
                ls += __shfl_xor_sync(0x000000ffu, ls, off);
            const float so = __expf(m_run - mt);
            l_run = l_run * so + ls;
            m_run = mt;
            if (lane < rows) pp[lane][h] = p;
            if (lane == 0) scl[h] = so;
        }
        __syncthreads();

        // ---- rescale + accumulate: thread owns f-pair f = 2*tid
        {
            float4 sl0 = *reinterpret_cast<const float4*>(&scl[0]);
            float4 sl1 = *reinterpret_cast<const float4*>(&scl[4]);
            acc[0].x *= sl0.x; acc[0].y *= sl0.x;
            acc[1].x *= sl0.y; acc[1].y *= sl0.y;
            acc[2].x *= sl0.z; acc[2].y *= sl0.z;
            acc[3].x *= sl0.w; acc[3].y *= sl0.w;
            acc[4].x *= sl1.x; acc[4].y *= sl1.x;
            acc[5].x *= sl1.y; acc[5].y *= sl1.y;
            acc[6].x *= sl1.z; acc[6].y *= sl1.z;
            acc[7].x *= sl1.w; acc[7].y *= sl1.w;
            const float2* xb = reinterpret_cast<const float2*>(tb) + tid;
#pragma unroll
            for (int t = 0; t < 8; t++) {
                if (t < rows) {
                    float2 xv = xb[t * (Fc / 2)];
                    float4 p0 = *reinterpret_cast<const float4*>(&pp[t][0]);
                    float4 p1 = *reinterpret_cast<const float4*>(&pp[t][4]);
                    acc[0] = fma2(acc[0], xv, make_float2(p0.x, p0.x));
                    acc[1] = fma2(acc[1], xv, make_float2(p0.y, p0.y));
                    acc[2] = fma2(acc[2], xv, make_float2(p0.z, p0.z));
                    acc[3] = fma2(acc[3], xv, make_float2(p0.w, p0.w));
                    acc[4] = fma2(acc[4], xv, make_float2(p1.x, p1.x));
                    acc[5] = fma2(acc[5], xv, make_float2(p1.y, p1.y));
                    acc[6] = fma2(acc[6], xv, make_float2(p1.z, p1.z));
                    acc[7] = fma2(acc[7], xv, make_float2(p1.w, p1.w));
                }
            }
        }
        __syncthreads();   // tile buffer free for reuse

        // ---- prefetch tile+2 into this buffer
        if (tile + 2 < NT) {
            const int t2 = tile + 2;
            const int nf4 = ((t2 == NT - 1) ? (CHUNK - 8 * (NT - 1)) : 8) * (Fc / 4);
            const float4* src = reinterpret_cast<const float4*>(xc) + t2 * (8 * Fc / 4);
            const unsigned int dst = (tile & 1) ? buf1 : buf0;
#pragma unroll
            for (int j = 0; j < 4; j++) {
                const int i = tid + 256 * j;
                if (i < nf4) cp16(dst + i * 16, src + i);
            }
        }
        CP_COMMIT();
    }

    // ---- epilogue: warp w owns head w's (m,l)
    if (lane == 0) { g_m[b][c][w] = m_run; g_l[b][c][w] = l_run; }
#pragma unroll
    for (int h = 0; h < 8; h++)
        *reinterpret_cast<float2*>(&g_acc[b][h][c][2 * tid]) = acc[h];
}

// ---------------- ctx (#5): per-(b,h) chunk combine + ctx = xa @ Wv[:,h,:] + bv ----------------
__global__ __launch_bounds__(256) void ctx_kernel(const float* __restrict__ Wv,
                                                  const float* __restrict__ bv) {
    __shared__ __align__(16) float xa[Fc];
    __shared__ float part[8][KDc];
    const int b = blockIdx.x >> 3;
    const int h = blockIdx.x & 7;
    const int tid = threadIdx.x;
    const int w = tid >> 5, lane = tid & 31;

    float M = NEGBIG;
#pragma unroll
    for (int c = 0; c < NCc; c++) M = fmaxf(M, g_m[b][c][h]);
    float ew[NCc];
    float L = 0.f;
#pragma unroll
    for (int c = 0; c < NCc; c++) {
        float e = __expf(g_m[b][c][h] - M);
        ew[c] = e;
        L += g_l[b][c][h] * e;
    }
    const float invL = 1.0f / L;

    float2 a = make_float2(0.f, 0.f);
    const float2* ap = reinterpret_cast<const float2*>(&g_acc[b][h][0][0]) + tid;
#pragma unroll
    for (int c = 0; c < NCc; c++) {
        float2 v = ap[c * (Fc / 2)];
        a = fma2(a, v, make_float2(ew[c], ew[c]));
    }
    a.x *= invL; a.y *= invL;
    *reinterpret_cast<float2*>(&xa[2 * tid]) = a;
    __syncthreads();

    {
        const float* wvp = Wv + h * KDc + lane;
        const int f0 = w * 64;
        float s0 = 0.f, s1 = 0.f, s2 = 0.f, s3 = 0.f;
#pragma unroll 4
        for (int i = 0; i < 64; i += 4) {
            s0 = fmaf(xa[f0 + i],     wvp[(f0 + i) * 256],     s0);
            s1 = fmaf(xa[f0 + i + 1], wvp[(f0 + i + 1) * 256], s1);
            s2 = fmaf(xa[f0 + i + 2], wvp[(f0 + i + 2) * 256], s2);
            s3 = fmaf(xa[f0 + i + 3], wvp[(f0 + i + 3) * 256], s3);
        }
        part[w][lane] = (s0 + s1) + (s2 + s3);
    }
    __syncthreads();
    if (tid < KDc) {
        float r = part[0][tid] + part[1][tid] + part[2][tid] + part[3][tid]
                + part[4][tid] + part[5][tid] + part[6][tid] + part[7][tid]
                + bv[h * KDc + tid];
        g_ctx[b][h * KDc + tid] = r;
    }
}

// ---------------- pooled (#6): pooled[b][f] = ctx[b,:] @ Wo + bo ----------------
__global__ __launch_bounds__(512) void pooled_kernel(const float* __restrict__ Wo,
                                                     const float* __restrict__ bo) {
    __shared__ float cs[Hc * KDc];
    const int b = blockIdx.x;
    const int tid = threadIdx.x;
    if (tid < 256) cs[tid] = g_ctx[b][tid];
    __syncthreads();

    const float* wp = Wo + tid;
    float s0 = 0.f, s1 = 0.f, s2 = 0.f, s3 = 0.f;
#pragma unroll 8
    for (int hk = 0; hk < 256; hk += 4) {
        s0 = fmaf(cs[hk],     wp[hk * 512],       s0);
        s1 = fmaf(cs[hk + 1], wp[(hk + 1) * 512], s1);
        s2 = fmaf(cs[hk + 2], wp[(hk + 2) * 512], s2);
        s3 = fmaf(cs[hk + 3], wp[(hk + 3) * 512], s3);
    }
    g_pooled[b][tid] = (s0 + s1) + (s2 + s3) + bo[tid];
}

// ---------------- dense_ln (#7): out = LayerNorm(pooled @ Wd) * gamma + beta ----------------
__global__ __launch_bounds__(512) void dense_ln_kernel(const float* __restrict__ Wd,
                                                       const float* __restrict__ gamma,
                                                       const float* __restrict__ beta,
                                                       float* __restrict__ out) {
    __shared__ float ps[Fc];
    __shared__ float red[32];
    __shared__ float stats[2];
    const int b = blockIdx.x;
    const int tid = threadIdx.x;

    ps[tid] = g_pooled[b][tid];
    __syncthreads();

    float v;
    {
        const float* wp = Wd + tid;
        float s0 = 0.f, s1 = 0.f, s2 = 0.f, s3 = 0.f;
#pragma unroll 8
        for (int f = 0; f < 512; f += 4) {
            s0 = fmaf(ps[f],     wp[f * 512],       s0);
            s1 = fmaf(ps[f + 1], wp[(f + 1) * 512], s1);
            s2 = fmaf(ps[f + 2], wp[(f + 2) * 512], s2);
            s3 = fmaf(ps[f + 3], wp[(f + 3) * 512], s3);
        }
        v = (s0 + s1) + (s2 + s3);
    }
    float s = v, s2 = v * v;
#pragma unroll
    for (int off = 16; off; off >>= 1) {
        s  += __shfl_xor_sync(0xffffffffu, s, off);
        s2 += __shfl_xor_sync(0xffffffffu, s2, off);
    }
    const int w = tid >> 5, lane = tid & 31;
    if (lane == 0) { red[w] = s; red[16 + w] = s2; }
    __syncthreads();
    if (tid == 0) {
        float ts = 0.f, ts2 = 0.f;
#pragma unroll
        for (int i = 0; i < 16; i++) { ts += red[i]; ts2 += red[16 + i]; }
        float mu = ts * (1.0f / 512.0f);
        float var = ts2 * (1.0f / 512.0f) - mu * mu;
        stats[0] = mu;
        stats[1] = rsqrtf(var + 1e-6f);
    }
    __syncthreads();
    out[b * 512 + tid] = (v - stats[0]) * stats[1] * gamma[tid] + beta[tid];
}

// ---------------- launch ----------------
extern "C" void kernel_launch(void* const* d_in, const int* in_sizes, int n_in,
                              void* d_out, int out_size) {
    const float* x     = (const float*)d_in[0];
    const float* q     = (const float*)d_in[1];
    const float* Wq    = (const float*)d_in[2];
    const float* bq    = (const float*)d_in[3];
    const float* Wk    = (const float*)d_in[4];
    const float* bk    = (const float*)d_in[5];
    const float* Wv    = (const float*)d_in[6];
    const float* bv    = (const float*)d_in[7];
    const float* Wo    = (const float*)d_in[8];
    const float* bo    = (const float*)d_in[9];
    const float* Wd    = (const float*)d_in[10];
    const float* gamma = (const float*)d_in[11];
    const float* beta  = (const float*)d_in[12];
    float* out = (float*)d_out;

    prep1_kernel<<<32, 256>>>(q, Wq);            // #1
    prep2_kernel<<<64, 256>>>(Wk, bq);           // #2
    prep_cb_kernel<<<1, 256>>>(bk, bq);          // #3
    main_kernel<<<dim3(NCc, Bc), 256>>>(x);      // #4  <- profiled slot
    ctx_kernel<<<Bc * Hc, 256>>>(Wv, bv);        // #5
    pooled_kernel<<<Bc, 512>>>(Wo, bo);          // #6
    dense_ln_kernel<<<Bc, 512>>>(Wd, gamma, beta, out);  // #7
}

// round 13
// speedup vs baseline: 1.0231x; 1.0231x over previous
#include <cuda_runtime.h>
#include <cuda_bf16.h>
#include <cstdint>

#define Bc    64
#define Tc    1000
#define Fc    512
#define Hc    8
#define KDc   32
#define NCc   8
#define CHUNK 125           // Tc / NCc
#define NT    16            // tiles per chunk (15 full x8 + 1 x5)
#define SCALE 0.17677669529663689f   // 1/sqrt(32)
#define NEGBIG (-3.4e38f)

// ---------------- device scratch (no allocation allowed) ----------------
__device__ float g_qpart[32][Hc * KDc];     // per-block partial qh sums
__device__ float g_wk[Hc][Fc];              // scale * (Wk @ qh), per head
__device__ float g_cb[Hc];                  // scale * (qh . bk)
__device__ float g_m[Bc][NCc][Hc];
__device__ float g_l[Bc][NCc][Hc];
__device__ float g_acc[Bc][Hc][NCc][Fc];    // 8.4 MB un-normalized weighted x sums
__device__ float g_ctx[Bc][Hc * KDc];
__device__ float g_pooled[Bc][Fc];

// ---------------- packed fp32x2 FMA (FFMA2) ----------------
__device__ __forceinline__ float2 fma2(float2 d, float2 a, float2 b) {
    unsigned long long dd, aa, bb;
    dd = *reinterpret_cast<unsigned long long*>(&d);
    aa = *reinterpret_cast<unsigned long long*>(&a);
    bb = *reinterpret_cast<unsigned long long*>(&b);
    asm("fma.rn.f32x2 %0, %1, %2, %0;" : "+l"(dd) : "l"(aa), "l"(bb));
    return *reinterpret_cast<float2*>(&dd);
}

__device__ __forceinline__ void cp16(unsigned int dst, const void* src) {
    asm volatile("cp.async.ca.shared.global [%0], [%1], 16;" :: "r"(dst), "l"(src));
}
#define CP_COMMIT() asm volatile("cp.async.commit_group;")
#define CP_WAIT1()  asm volatile("cp.async.wait_group 1;")

// ---------------- prep1 (#1): partial qh sums, 32 blocks over f-chunks ----------------
__global__ __launch_bounds__(256) void prep1_kernel(const float* __restrict__ q,
                                                    const float* __restrict__ Wq) {
    const int tid = threadIdx.x;
    const int f0 = blockIdx.x * 16;
    float qv[16];
#pragma unroll
    for (int ff = 0; ff < 16; ff++) qv[ff] = q[f0 + ff];
    float s = 0.f;
#pragma unroll
    for (int ff = 0; ff < 16; ff++)
        s = fmaf(qv[ff], Wq[(f0 + ff) * 256 + tid], s);
    g_qpart[blockIdx.x][tid] = s;
}

// ---------------- prep2 (#2): wk_eff[h][f] = scale * sum_k Wk[f,h,k]*qh[h,k] ----------------
__global__ __launch_bounds__(256) void prep2_kernel(const float* __restrict__ Wk,
                                                    const float* __restrict__ bq) {
    __shared__ float qh[Hc * KDc];
    const int tid = threadIdx.x;
    {
        float s = bq[tid];
#pragma unroll
        for (int i = 0; i < 32; i++) s += g_qpart[i][tid];
        qh[tid] = s;
    }
    __syncthreads();

    const int f0 = blockIdx.x * 8;
    const int o = tid >> 2;          // 0..63 : (frow, h)
    const int sub = tid & 3;         // k-quarter
    const int f = f0 + (o >> 3);
    const int h = o & 7;
    const float4* Wk4 = reinterpret_cast<const float4*>(Wk);
    float4 w0 = Wk4[f * 64 + h * 8 + sub * 2];
    float4 w1 = Wk4[f * 64 + h * 8 + sub * 2 + 1];
    const float* qp = &qh[h * 32 + sub * 8];
    float s = w0.x * qp[0] + w0.y * qp[1] + w0.z * qp[2] + w0.w * qp[3]
            + w1.x * qp[4] + w1.y * qp[5] + w1.z * qp[6] + w1.w * qp[7];
    s += __shfl_xor_sync(0xffffffffu, s, 1);
    s += __shfl_xor_sync(0xffffffffu, s, 2);
    if (sub == 0) g_wk[h][f] = s * SCALE;
}

// ---------------- prep_cb (#3): cb[h] = scale * (qh[h,:] . bk[h,:]) ----------------
__global__ __launch_bounds__(256) void prep_cb_kernel(const float* __restrict__ bk,
                                                      const float* __restrict__ bq) {
    __shared__ float qh[Hc * KDc];
    const int tid = threadIdx.x;
    {
        float s = bq[tid];
#pragma unroll
        for (int i = 0; i < 32; i++) s += g_qpart[i][tid];
        qh[tid] = s;
    }
    __syncthreads();
    if (tid < 8) {
        float c = 0.f;
        for (int k = 0; k < 32; k++) c += bk[tid * 32 + k] * qh[tid * 32 + k];
        g_cb[tid] = c * SCALE;
    }
}

// ---------------- main (#4): single-pass online-softmax, 4 blocks/SM ----------------
__global__ __launch_bounds__(256, 4) void main_kernel(const float* __restrict__ x) {
    __shared__ __align__(16) float buf[2][8 * Fc];    // 32 KB double buffer
    __shared__ __align__(16) float scp[8][8][8];      // [row][head][fh*4+group] partials
    __shared__ __align__(16) float pp[8][8];          // exp weights of current tile
    __shared__ __align__(16) float scl[8];            // per-head acc rescale
    const int tid = threadIdx.x;
    const int w = tid >> 5, lane = tid & 31;
    const int b = blockIdx.y, c = blockIdx.x;
    const float* xc = x + ((size_t)b * Tc + c * CHUNK) * Fc;

    const unsigned int buf0 = (unsigned int)__cvta_generic_to_shared(&buf[0][0]);
    const unsigned int buf1 = (unsigned int)__cvta_generic_to_shared(&buf[1][0]);

    // ---- score warp role: (head-pair, f-half); each warp does ALL 8 rows
    const int hp = w & 3;            // heads {2hp, 2hp+1}
    const int fh = w >> 2;           // f in [fh*256, fh*256+256)
    // per-lane wk: 2 heads x 8 f (f = fh*256 + 4*lane + {0..3, 128..131})
    float2 wk2[2][4];
#pragma unroll
    for (int i = 0; i < 2; i++) {
        float4 a0 = *reinterpret_cast<const float4*>(&g_wk[2 * hp + i][fh * 256 + 4 * lane]);
        float4 a1 = *reinterpret_cast<const float4*>(&g_wk[2 * hp + i][fh * 256 + 128 + 4 * lane]);
        wk2[i][0] = make_float2(a0.x, a0.y);
        wk2[i][1] = make_float2(a0.z, a0.w);
        wk2[i][2] = make_float2(a1.x, a1.y);
        wk2[i][3] = make_float2(a1.z, a1.w);
    }
    const float cbh = g_cb[w];       // head-w bias for the softmax stage
    // score partial store role: lanes 0-7 write (head, group)
    const int st_head = 2 * hp + (lane >> 2);   // lanes 0-3 -> head0, 4-7 -> head1
    const int st_slot = fh * 4 + (lane & 3);    // group index

    // ---- prologue: preload tiles 0 and 1
    {
        const float4* src = reinterpret_cast<const float4*>(xc);
#pragma unroll
        for (int j = 0; j < 4; j++) cp16(buf0 + (tid + 256 * j) * 16, src + tid + 256 * j);
        CP_COMMIT();
#pragma unroll
        for (int j = 0; j < 4; j++) cp16(buf1 + (tid + 256 * j) * 16, src + 1024 + tid + 256 * j);
        CP_COMMIT();
    }

    float2 acc[8];
#pragma unroll
    for (int h = 0; h < 8; h++) acc[h] = make_float2(0.f, 0.f);
    float m_run = NEGBIG, l_run = 0.f;   // per-warp: warp w owns head w (lanes 0-7)

    for (int tile = 0; tile < NT; tile++) {
        const int rows = (tile == NT - 1) ? (CHUNK - 8 * (NT - 1)) : 8;
        float* tb = buf[tile & 1];

        CP_WAIT1();
        __syncthreads();

        // ---- score partials: 8 rows x 2 heads x 256 f per warp; 3-stage reduce
#pragma unroll
        for (int r = 0; r < 8; r++) {
            if (r < rows) {
                const float* xr = tb + r * Fc + fh * 256 + 4 * lane;
                float4 x0 = *reinterpret_cast<const float4*>(xr);
                float4 x1 = *reinterpret_cast<const float4*>(xr + 128);
                float2 p0 = make_float2(0.f, 0.f), p1 = make_float2(0.f, 0.f);
                p0 = fma2(p0, make_float2(x0.x, x0.y), wk2[0][0]);
                p0 = fma2(p0, make_float2(x0.z, x0.w), wk2[0][1]);
                p0 = fma2(p0, make_float2(x1.x, x1.y), wk2[0][2]);
                p0 = fma2(p0, make_float2(x1.z, x1.w), wk2[0][3]);
                p1 = fma2(p1, make_float2(x0.x, x0.y), wk2[1][0]);
                p1 = fma2(p1, make_float2(x0.z, x0.w), wk2[1][1]);
                p1 = fma2(p1, make_float2(x1.x, x1.y), wk2[1][2]);
                p1 = fma2(p1, make_float2(x1.z, x1.w), wk2[1][3]);
                float s0 = p0.x + p0.y, s1 = p1.x + p1.y;
#pragma unroll
                for (int off = 16; off >= 4; off >>= 1) {   // 3 stages -> 4 group partials
                    s0 += __shfl_xor_sync(0xffffffffu, s0, off);
                    s1 += __shfl_xor_sync(0xffffffffu, s1, off);
                }
                if (lane < 8)
                    scp[r][st_head][st_slot] = (lane < 4) ? s0 : s1;
            }
        }
        __syncthreads();

        // ---- online softmax, 8-way parallel: warp w = head w, lanes 0-7 = rows
        if (lane < 8) {
            const int h = w;
            float s;
            if (lane < rows) {
                float4 g0 = *reinterpret_cast<const float4*>(&scp[lane][h][0]);
                float4 g1 = *reinterpret_cast<const float4*>(&scp[lane][h][4]);
                s = ((g0.x + g0.y) + (g0.z + g0.w))
                  + ((g1.x + g1.y) + (g1.z + g1.w)) + cbh;
            } else {
                s = NEGBIG;
            }
            float mt = fmaxf(s, m_run);
#pragma unroll
            for (int off = 4; off; off >>= 1)
                mt = fmaxf(mt, __shfl_xor_sync(0x000000ffu, mt, off));
            float p = __expf(s - mt);          // 0 for padding lanes
            float ls = p;
#pragma unroll
            for (int off = 4; off; off >>= 1)
                ls += __shfl_xor_sync(0x000000ffu, ls, off);
            const float so = __expf(m_run - mt);
            l_run = l_run * so + ls;
            m_run = mt;
            if (lane < rows) pp[lane][h] = p;
            if (lane == 0) scl[h] = so;
        }
        __syncthreads();

        // ---- rescale + accumulate: thread owns f-pair f = 2*tid
        {
            float4 sl0 = *reinterpret_cast<const float4*>(&scl[0]);
            float4 sl1 = *reinterpret_cast<const float4*>(&scl[4]);
            acc[0].x *= sl0.x; acc[0].y *= sl0.x;
            acc[1].x *= sl0.y; acc[1].y *= sl0.y;
            acc[2].x *= sl0.z; acc[2].y *= sl0.z;
            acc[3].x *= sl0.w; acc[3].y *= sl0.w;
            acc[4].x *= sl1.x; acc[4].y *= sl1.x;
            acc[5].x *= sl1.y; acc[5].y *= sl1.y;
            acc[6].x *= sl1.z; acc[6].y *= sl1.z;
            acc[7].x *= sl1.w; acc[7].y *= sl1.w;
            const float2* xb = reinterpret_cast<const float2*>(tb) + tid;
#pragma unroll
            for (int t = 0; t < 8; t++) {
                if (t < rows) {
                    float2 xv = xb[t * (Fc / 2)];
                    float4 p0 = *reinterpret_cast<const float4*>(&pp[t][0]);
                    float4 p1 = *reinterpret_cast<const float4*>(&pp[t][4]);
                    acc[0] = fma2(acc[0], xv, make_float2(p0.x, p0.x));
                    acc[1] = fma2(acc[1], xv, make_float2(p0.y, p0.y));
                    acc[2] = fma2(acc[2], xv, make_float2(p0.z, p0.z));
                    acc[3] = fma2(acc[3], xv, make_float2(p0.w, p0.w));
                    acc[4] = fma2(acc[4], xv, make_float2(p1.x, p1.x));
                    acc[5] = fma2(acc[5], xv, make_float2(p1.y, p1.y));
                    acc[6] = fma2(acc[6], xv, make_float2(p1.z, p1.z));
                    acc[7] = fma2(acc[7], xv, make_float2(p1.w, p1.w));
                }
            }
        }
        __syncthreads();   // tile buffer free for reuse

        // ---- prefetch tile+2 into this buffer
        if (tile + 2 < NT) {
            const int t2 = tile + 2;
            const int nf4 = ((t2 == NT - 1) ? (CHUNK - 8 * (NT - 1)) : 8) * (Fc / 4);
            const float4* src = reinterpret_cast<const float4*>(xc) + t2 * (8 * Fc / 4);
            const unsigned int dst = (tile & 1) ? buf1 : buf0;
#pragma unroll
            for (int j = 0; j < 4; j++) {
                const int i = tid + 256 * j;
                if (i < nf4) cp16(dst + i * 16, src + i);
            }
        }
        CP_COMMIT();
    }

    // ---- epilogue: warp w owns head w's (m,l)
    if (lane == 0) { g_m[b][c][w] = m_run; g_l[b][c][w] = l_run; }
#pragma unroll
    for (int h = 0; h < 8; h++)
        *reinterpret_cast<float2*>(&g_acc[b][h][c][2 * tid]) = acc[h];
}

// ---------------- ctx (#5): per-(b,h) chunk combine + ctx = xa @ Wv[:,h,:] + bv ----------------
__global__ __launch_bounds__(256) void ctx_kernel(const float* __restrict__ Wv,
                                                  const float* __restrict__ bv) {
    __shared__ __align__(16) float xa[Fc];
    __shared__ float part[8][KDc];
    const int b = blockIdx.x >> 3;
    const int h = blockIdx.x & 7;
    const int tid = threadIdx.x;
    const int w = tid >> 5, lane = tid & 31;

    float M = NEGBIG;
#pragma unroll
    for (int c = 0; c < NCc; c++) M = fmaxf(M, g_m[b][c][h]);
    float ew[NCc];
    float L = 0.f;
#pragma unroll
    for (int c = 0; c < NCc; c++) {
        float e = __expf(g_m[b][c][h] - M);
        ew[c] = e;
        L += g_l[b][c][h] * e;
    }
    const float invL = 1.0f / L;

    float2 a = make_float2(0.f, 0.f);
    const float2* ap = reinterpret_cast<const float2*>(&g_acc[b][h][0][0]) + tid;
#pragma unroll
    for (int c = 0; c < NCc; c++) {
        float2 v = ap[c * (Fc / 2)];
        a = fma2(a, v, make_float2(ew[c], ew[c]));
    }
    a.x *= invL; a.y *= invL;
    *reinterpret_cast<float2*>(&xa[2 * tid]) = a;
    __syncthreads();

    {
        const float* wvp = Wv + h * KDc + lane;
        const int f0 = w * 64;
        float s0 = 0.f, s1 = 0.f, s2 = 0.f, s3 = 0.f;
#pragma unroll 4
        for (int i = 0; i < 64; i += 4) {
            s0 = fmaf(xa[f0 + i],     wvp[(f0 + i) * 256],     s0);
            s1 = fmaf(xa[f0 + i + 1], wvp[(f0 + i + 1) * 256], s1);
            s2 = fmaf(xa[f0 + i + 2], wvp[(f0 + i + 2) * 256], s2);
            s3 = fmaf(xa[f0 + i + 3], wvp[(f0 + i + 3) * 256], s3);
        }
        part[w][lane] = (s0 + s1) + (s2 + s3);
    }
    __syncthreads();
    if (tid < KDc) {
        float r = part[0][tid] + part[1][tid] + part[2][tid] + part[3][tid]
                + part[4][tid] + part[5][tid] + part[6][tid] + part[7][tid]
                + bv[h * KDc + tid];
        g_ctx[b][h * KDc + tid] = r;
    }
}

// ---------------- pooled (#6): pooled[b][f] = ctx[b,:] @ Wo + bo ----------------
__global__ __launch_bounds__(512) void pooled_kernel(const float* __restrict__ Wo,
                                                     const float* __restrict__ bo) {
    __shared__ float cs[Hc * KDc];
    const int b = blockIdx.x;
    const int tid = threadIdx.x;
    if (tid < 256) cs[tid] = g_ctx[b][tid];
    __syncthreads();

    const float* wp = Wo + tid;
    float s0 = 0.f, s1 = 0.f, s2 = 0.f, s3 = 0.f;
#pragma unroll 8
    for (int hk = 0; hk < 256; hk += 4) {
        s0 = fmaf(cs[hk],     wp[hk * 512],       s0);
        s1 = fmaf(cs[hk + 1], wp[(hk + 1) * 512], s1);
        s2 = fmaf(cs[hk + 2], wp[(hk + 2) * 512], s2);
        s3 = fmaf(cs[hk + 3], wp[(hk + 3) * 512], s3);
    }
    g_pooled[b][tid] = (s0 + s1) + (s2 + s3) + bo[tid];
}

// ---------------- dense_ln (#7): out = LayerNorm(pooled @ Wd) * gamma + beta ----------------
__global__ __launch_bounds__(512) void dense_ln_kernel(const float* __restrict__ Wd,
                                                       const float* __restrict__ gamma,
                                                       const float* __restrict__ beta,
                                                       float* __restrict__ out) {
    __shared__ float ps[Fc];
    __shared__ float red[32];
    __shared__ float stats[2];
    const int b = blockIdx.x;
    const int tid = threadIdx.x;

    ps[tid] = g_pooled[b][tid];
    __syncthreads();

    float v;
    {
        const float* wp = Wd + tid;
        float s0 = 0.f, s1 = 0.f, s2 = 0.f, s3 = 0.f;
#pragma unroll 8
        for (int f = 0; f < 512; f += 4) {
            s0 = fmaf(ps[f],     wp[f * 512],       s0);
            s1 = fmaf(ps[f + 1], wp[(f + 1) * 512], s1);
            s2 = fmaf(ps[f + 2], wp[(f + 2) * 512], s2);
            s3 = fmaf(ps[f + 3], wp[(f + 3) * 512], s3);
        }
        v = (s0 + s1) + (s2 + s3);
    }
    float s = v, s2 = v * v;
#pragma unroll
    for (int off = 16; off; off >>= 1) {
        s  += __shfl_xor_sync(0xffffffffu, s, off);
        s2 += __shfl_xor_sync(0xffffffffu, s2, off);
    }
    const int w = tid >> 5, lane = tid & 31;
    if (lane == 0) { red[w] = s; red[16 + w] = s2; }
    __syncthreads();
    if (tid == 0) {
        float ts = 0.f, ts2 = 0.f;
#pragma unroll
        for (int i = 0; i < 16; i++) { ts += red[i]; ts2 += red[16 + i]; }
        float mu = ts * (1.0f / 512.0f);
        float var = ts2 * (1.0f / 512.0f) - mu * mu;
        stats[0] = mu;
        stats[1] = rsqrtf(var + 1e-6f);
    }
    __syncthreads();
    out[b * 512 + tid] = (v - stats[0]) * stats[1] * gamma[tid] + beta[tid];
}

// ---------------- launch ----------------
extern "C" void kernel_launch(void* const* d_in, const int* in_sizes, int n_in,
                              void* d_out, int out_size) {
    const float* x     = (const float*)d_in[0];
    const float* q     = (const float*)d_in[1];
    const float* Wq    = (const float*)d_in[2];
    const float* bq    = (const float*)d_in[3];
    const float* Wk    = (const float*)d_in[4];
    const float* bk    = (const float*)d_in[5];
    const float* Wv    = (const float*)d_in[6];
    const float* bv    = (const float*)d_in[7];
    const float* Wo    = (const float*)d_in[8];
    const float* bo    = (const float*)d_in[9];
    const float* Wd    = (const float*)d_in[10];
    const float* gamma = (const float*)d_in[11];
    const float* beta  = (const float*)d_in[12];
    float* out = (float*)d_out;

    prep1_kernel<<<32, 256>>>(q, Wq);            // #1
    prep2_kernel<<<64, 256>>>(Wk, bq);           // #2
    prep_cb_kernel<<<1, 256>>>(bk, bq);          // #3
    main_kernel<<<dim3(NCc, Bc), 256>>>(x);      // #4  <- profiled slot
    ctx_kernel<<<Bc * Hc, 256>>>(Wv, bv);        // #5
    pooled_kernel<<<Bc, 512>>>(Wo, bo);          // #6
    dense_ln_kernel<<<Bc, 512>>>(Wd, gamma, beta, out);  // #7
}